// round 10
// baseline (speedup 1.0000x reference)
#include <cuda_runtime.h>
#include <math.h>

#define NA 192
#define TT 80
#define NC 5
#define THREADS 512
#define NTILE 21            // upper-triangular 32x32 tiles of 192x192
#define TPB 3               // tiles per block
#define NBLK (NTILE / TPB)  // 7
#define PLANE (NC * NA)     // 960 floats per coordinate plane
#define TP 33               // transpose tile pitch (conflict-free)

__constant__ int c_bi[NTILE] = {0,0,0,0,0,0, 1,1,1,1,1, 2,2,2,2, 3,3,3, 4,4, 5};
__constant__ int c_bj[NTILE] = {0,1,2,3,4,5, 1,2,3,4,5, 2,3,4,5, 3,4,5, 4,5, 5};

// packed {-v, -v}
#define PACK_NEG2(dst, v) \
    asm("mov.b64 %0, {%1, %1};" : "=l"(dst) : "f"(-(v)))

// two squared distances (packed f32x2) + scalar running mins on the halves
#define CIRC2(mlo, mhi, xj, nxi, yj, nyi)                         \
    asm("{\n\t"                                                   \
        ".reg .b64 dx, dy, d2;\n\t"                               \
        ".reg .f32 lo, hi;\n\t"                                   \
        "add.rn.f32x2 dx, %2, %3;\n\t"                            \
        "add.rn.f32x2 dy, %4, %5;\n\t"                            \
        "mul.rn.f32x2 d2, dy, dy;\n\t"                            \
        "fma.rn.f32x2 d2, dx, dx, d2;\n\t"                        \
        "mov.b64 {lo, hi}, d2;\n\t"                               \
        "min.f32 %0, %0, lo;\n\t"                                 \
        "min.f32 %1, %1, hi;\n\t"                                 \
        "}"                                                       \
        : "+f"(mlo), "+f"(mhi)                                    \
        : "l"(xj), "l"(nxi), "l"(yj), "l"(nyi))

// ---- single fused kernel: build slab once, then 3 pair tiles ----
__global__ void __launch_bounds__(THREADS)
veh_kernel(const float* __restrict__ traj,   // (NA, T, 4)
           const float* __restrict__ cent,   // (NA, NC, 4)
           const float* __restrict__ pd,     // (NA, NA)
           float* __restrict__ out)
{
    const int t   = blockIdx.y;
    const int tid = threadIdx.x;

    __shared__ __align__(16) float s[2 * PLANE];     // world x then y (7.5 KB)
    __shared__ float tpen[32 * TP];
    __shared__ float tmsk[32 * TP];
    float* __restrict__ swx = s;
    float* __restrict__ swy = s + PLANE;

    // ---- build world circles for all 192 agents at this t ----
    if (tid < NA) {
        const int a = tid;
        const float4 tr = *reinterpret_cast<const float4*>(traj + ((size_t)a * TT + t) * 4);
        float hx = tr.z, hy = tr.w;
        const float inv = rsqrtf(hx * hx + hy * hy);
        hx *= inv; hy *= inv;
        #pragma unroll
        for (int c = 0; c < NC; ++c) {
            const float2 cc = *reinterpret_cast<const float2*>(cent + ((size_t)a * NC + c) * 4);
            swx[c * NA + a] = fmaf(hx, cc.x, fmaf(-hy, cc.y, tr.x));
            swy[c * NA + a] = fmaf(hy, cc.x, fmaf( hx, cc.y, tr.y));
        }
    }
    __syncthreads();

    const int r = tid >> 4;          // local i row 0..31
    const int p = tid & 15;          // j-pair column 0..15
    const size_t tbase = (size_t)t * (NA * NA);
    const size_t moff  = (size_t)TT * (NA * NA);

    #pragma unroll 1
    for (int it = 0; it < TPB; ++it) {
        const int tile = blockIdx.x * TPB + it;
        const int bi = c_bi[tile];
        const int bj = c_bj[tile];
        const int i  = bi * 32 + r;
        const int j0 = bj * 32 + p * 2;

        // packed {-xi,-xi},{-yi,-yi} per circle (broadcast LDS)
        unsigned long long nxi[NC], nyi[NC];
        #pragma unroll
        for (int c = 0; c < NC; ++c) {
            PACK_NEG2(nxi[c], swx[c * NA + i]);
            PACK_NEG2(nyi[c], swy[c * NA + i]);
        }

        // scalar min accumulators split by c-parity: shorter RAW chains
        float m0a = 3.4e38f, m1a = 3.4e38f;
        float m0b = 3.4e38f, m1b = 3.4e38f;

        #pragma unroll
        for (int d = 0; d < NC; ++d) {
            const unsigned long long xj = *reinterpret_cast<const unsigned long long*>(swx + d * NA + j0);
            const unsigned long long yj = *reinterpret_cast<const unsigned long long*>(swy + d * NA + j0);
            #pragma unroll
            for (int c = 0; c < NC; ++c) {
                if (c & 1) { CIRC2(m0b, m1b, xj, nxi[c], yj, nyi[c]); }
                else       { CIRC2(m0a, m1a, xj, nxi[c], yj, nyi[c]); }
            }
        }

        float mv[2];
        mv[0] = fminf(m0a, m0b);
        mv[1] = fminf(m1a, m1b);

        const int idx = i * NA + j0;
        const float2 p2 = *reinterpret_cast<const float2*>(pd + idx);
        const float pv[2] = {p2.x, p2.y};

        float2 pen, msk;
        float* penp = &pen.x;
        float* mskp = &msk.x;
        #pragma unroll
        for (int k = 0; k < 2; ++k) {
            const float m2e = mv[k] + 1e-30f;      // diagonal-zero guard for rsqrt
            float rr, ip;
            asm("rsqrt.approx.f32 %0, %1;" : "=f"(rr) : "f"(m2e));
            asm("rcp.approx.f32 %0, %1;"   : "=f"(ip) : "f"(pv[k]));
            const float mind = m2e * rr;           // = sqrt(m2e)
            penp[k] = fmaf(-mind, ip, 1.0f);
            // sqrt monotone: mind <= p  <=>  m2 <= p^2 ; diagonal excluded by i != j
            mskp[k] = (mv[k] <= pv[k] * pv[k] && i != j0 + k) ? 1.0f : 0.0f;
        }

        // direct tile write
        *reinterpret_cast<float2*>(out + tbase + idx) = pen;
        *reinterpret_cast<float2*>(out + moff + tbase + idx) = msk;

        // mirrored tile write (off-diagonal tiles only; block-uniform branch)
        if (bi != bj) {
            __syncthreads();    // protect tpen/tmsk reuse across iterations
            #pragma unroll
            for (int k = 0; k < 2; ++k) {
                tpen[(p * 2 + k) * TP + r] = penp[k];   // [local j][local i]
                tmsk[(p * 2 + k) * TP + r] = mskp[k];
            }
            __syncthreads();

            float2 vp, vm;
            float* vpp = &vp.x;
            float* vmp = &vm.x;
            #pragma unroll
            for (int k = 0; k < 2; ++k) {
                vpp[k] = tpen[r * TP + p * 2 + k];
                vmp[k] = tmsk[r * TP + p * 2 + k];
            }
            const int ot = (bj * 32 + r) * NA + bi * 32 + p * 2;
            *reinterpret_cast<float2*>(out + tbase + ot) = vp;
            *reinterpret_cast<float2*>(out + moff + tbase + ot) = vm;
        }
    }
}

extern "C" void kernel_launch(void* const* d_in, const int* in_sizes, int n_in,
                              void* d_out, int out_size)
{
    const float* traj = (const float*)d_in[0];   // (192,80,4)
    const float* cent = (const float*)d_in[1];   // (192,5,4)
    const float* pd   = (const float*)d_in[2];   // (192,192)

    dim3 grid(NBLK, TT);   // (7, 80) = 560 blocks — single launch
    veh_kernel<<<grid, THREADS>>>(traj, cent, pd, (float*)d_out);
}

// round 11
// speedup vs baseline: 1.1335x; 1.1335x over previous
#include <cuda_runtime.h>
#include <math.h>

#define NA 192
#define TT 80
#define NC 5
#define THREADS 256
#define NTILE 21            // upper-triangular 32x32 tiles of 192x192
#define TPB 3               // tiles per block
#define NBLK (NTILE / TPB)  // 7
#define PLANE (NC * NA)     // 960 floats per coordinate plane
#define TP 33               // transpose tile pitch (conflict-free)

typedef unsigned long long u64;

__constant__ int c_bi[NTILE] = {0,0,0,0,0,0, 1,1,1,1,1, 2,2,2,2, 3,3,3, 4,4, 5};
__constant__ int c_bj[NTILE] = {0,1,2,3,4,5, 1,2,3,4,5, 2,3,4,5, 3,4,5, 4,5, 5};

#define PK2(dst, v)   asm("mov.b64 %0, {%1, %1};" : "=l"(dst) : "f"(v))
#define SUB2(d,a,b)   asm("sub.rn.f32x2 %0, %1, %2;" : "=l"(d) : "l"(a), "l"(b))
#define MUL2(d,a,b)   asm("mul.rn.f32x2 %0, %1, %2;" : "=l"(d) : "l"(a), "l"(b))
#define ADD2(d,a,b)   asm("add.rn.f32x2 %0, %1, %2;" : "=l"(d) : "l"(a), "l"(b))
#define FMA2(d,a,b,c) asm("fma.rn.f32x2 %0, %1, %2, %3;" : "=l"(d) : "l"(a), "l"(b), "l"(c))
#define FMA2ACC(acc,a,b) asm("fma.rn.f32x2 %0, %1, %2, %0;" : "+l"(acc) : "l"(a), "l"(b))
#define ADD2ACC(acc,b)   asm("add.rn.f32x2 %0, %0, %1;" : "+l"(acc) : "l"(b))
#define MINS(mlo,mhi,v)                                           \
    asm("{\n\t.reg .f32 lo, hi;\n\t"                              \
        "mov.b64 {lo, hi}, %2;\n\t"                               \
        "min.f32 %0, %0, lo;\n\t"                                 \
        "min.f32 %1, %1, hi;\n\t}"                                \
        : "+f"(mlo), "+f"(mhi) : "l"(v))

// one j-circle plane (d) against all 5 i-circles via affine recurrence in c
__device__ __forceinline__ void dblock(
    u64 xjh, u64 yjh, u64 xi02, u64 yi02,
    u64 hx2, u64 hy2, u64 ms2, u64 mtwos2, u64 mhalfs2,
    float& mEl, float& mEh, float& mOl, float& mOh)
{
    u64 dx, dy, tt, d2, g, gh;
    SUB2(dx, xjh, xi02);
    SUB2(dy, yjh, yi02);
    MUL2(tt, dx, dx);
    FMA2(d2, dy, dy, tt);          // d2 at c=0
    MUL2(g, hx2, dx);
    FMA2(g, hy2, dy, g);           // g = h_i . (w_j - w_i(0))
    ADD2(gh, g, mhalfs2);          // gh = g - s/2
    MINS(mEl, mEh, d2);            // c = 0 (even chain)
    #pragma unroll
    for (int c = 1; c < NC; ++c) {
        FMA2ACC(d2, mtwos2, gh);   // d2 += -2s * gh
        ADD2ACC(gh, ms2);          // gh += -s
        if (c & 1) { MINS(mOl, mOh, d2); }
        else       { MINS(mEl, mEh, d2); }
    }
}

// ---- single fused kernel: build slab once, then 3 pair tiles ----
__global__ void __launch_bounds__(THREADS)
veh_kernel(const float* __restrict__ traj,   // (NA, T, 4)
           const float* __restrict__ cent,   // (NA, NC, 4)
           const float* __restrict__ pd,     // (NA, NA)
           float* __restrict__ out)
{
    const int t   = blockIdx.y;
    const int tid = threadIdx.x;

    __shared__ __align__(16) float s[2 * PLANE];     // world x then y (7.5 KB)
    __shared__ float shx[NA], shy[NA], ss[NA];       // heading + circle step
    __shared__ float tpen[32 * TP];
    __shared__ float tmsk[32 * TP];
    float* __restrict__ swx = s;
    float* __restrict__ swy = s + PLANE;

    // ---- build world circles + per-agent recurrence constants ----
    if (tid < NA) {
        const int a = tid;
        const float4 tr = *reinterpret_cast<const float4*>(traj + ((size_t)a * TT + t) * 4);
        float hx = tr.z, hy = tr.w;
        const float inv = rsqrtf(hx * hx + hy * hy);
        hx *= inv; hy *= inv;
        float cx0 = 0.f, cx1 = 0.f;
        #pragma unroll
        for (int c = 0; c < NC; ++c) {
            const float2 cc = *reinterpret_cast<const float2*>(cent + ((size_t)a * NC + c) * 4);
            if (c == 0) cx0 = cc.x;
            if (c == 1) cx1 = cc.x;
            swx[c * NA + a] = fmaf(hx, cc.x, fmaf(-hy, cc.y, tr.x));
            swy[c * NA + a] = fmaf(hy, cc.x, fmaf( hx, cc.y, tr.y));
        }
        shx[a] = hx;
        shy[a] = hy;
        ss[a]  = cx1 - cx0;     // arithmetic spacing of circles along heading
    }
    __syncthreads();

    const int r = tid >> 3;          // local i row 0..31
    const int q = tid & 7;           // quad column 0..7
    const size_t tbase = (size_t)t * (NA * NA);
    const size_t moff  = (size_t)TT * (NA * NA);

    #pragma unroll 1
    for (int it = 0; it < TPB; ++it) {
        const int tile = blockIdx.x * TPB + it;
        const int bi = c_bi[tile];
        const int bj = c_bj[tile];
        const int i  = bi * 32 + r;
        const int j0 = bj * 32 + q * 4;

        // i-state: c=0 circle, heading, negated step constants (packed)
        const float si = ss[i];
        u64 xi02, yi02, hx2, hy2, ms2, mtwos2, mhalfs2;
        PK2(xi02, swx[i]);           // plane c=0
        PK2(yi02, swy[i]);
        PK2(hx2, shx[i]);
        PK2(hy2, shy[i]);
        PK2(ms2, -si);
        ADD2(mtwos2, ms2, ms2);      // -2s
        PK2(mhalfs2, -0.5f * si);    // -s/2

        float m0E = 3.4e38f, m1E = 3.4e38f, m2E = 3.4e38f, m3E = 3.4e38f;
        float m0O = 3.4e38f, m1O = 3.4e38f, m2O = 3.4e38f, m3O = 3.4e38f;

        #pragma unroll
        for (int d = 0; d < NC; ++d) {
            const ulonglong2 xj = *reinterpret_cast<const ulonglong2*>(swx + d * NA + j0);
            const ulonglong2 yj = *reinterpret_cast<const ulonglong2*>(swy + d * NA + j0);
            dblock(xj.x, yj.x, xi02, yi02, hx2, hy2, ms2, mtwos2, mhalfs2,
                   m0E, m1E, m0O, m1O);
            dblock(xj.y, yj.y, xi02, yi02, hx2, hy2, ms2, mtwos2, mhalfs2,
                   m2E, m3E, m2O, m3O);
        }

        float mv[4];
        mv[0] = fminf(m0E, m0O);
        mv[1] = fminf(m1E, m1O);
        mv[2] = fminf(m2E, m2O);
        mv[3] = fminf(m3E, m3O);

        const int idx = i * NA + j0;
        const float4 p4 = *reinterpret_cast<const float4*>(pd + idx);
        const float pv[4] = {p4.x, p4.y, p4.z, p4.w};

        float4 pen, msk;
        float* penp = &pen.x;
        float* mskp = &msk.x;
        #pragma unroll
        for (int k = 0; k < 4; ++k) {
            // clamp (recurrence can give tiny negatives on the diagonal) + rsqrt guard
            const float m2e = fmaxf(mv[k], 0.0f) + 1e-30f;
            float rr, ip;
            asm("rsqrt.approx.f32 %0, %1;" : "=f"(rr) : "f"(m2e));
            asm("rcp.approx.f32 %0, %1;"   : "=f"(ip) : "f"(pv[k]));
            const float mind = m2e * rr;           // = sqrt(m2e)
            penp[k] = fmaf(-mind, ip, 1.0f);
            // sqrt monotone: mind <= p  <=>  m2 <= p^2 ; diagonal excluded by i != j
            mskp[k] = (mv[k] <= pv[k] * pv[k] && i != j0 + k) ? 1.0f : 0.0f;
        }

        // direct tile write
        *reinterpret_cast<float4*>(out + tbase + idx) = pen;
        *reinterpret_cast<float4*>(out + moff + tbase + idx) = msk;

        // mirrored tile write (off-diagonal tiles only; block-uniform branch)
        if (bi != bj) {
            __syncthreads();    // protect tpen/tmsk reuse across iterations
            #pragma unroll
            for (int k = 0; k < 4; ++k) {
                tpen[(q * 4 + k) * TP + r] = penp[k];   // [local j][local i]
                tmsk[(q * 4 + k) * TP + r] = mskp[k];
            }
            __syncthreads();

            float4 vp, vm;
            float* vpp = &vp.x;
            float* vmp = &vm.x;
            #pragma unroll
            for (int k = 0; k < 4; ++k) {
                vpp[k] = tpen[r * TP + q * 4 + k];
                vmp[k] = tmsk[r * TP + q * 4 + k];
            }
            const int ot = (bj * 32 + r) * NA + bi * 32 + q * 4;
            *reinterpret_cast<float4*>(out + tbase + ot) = vp;
            *reinterpret_cast<float4*>(out + moff + tbase + ot) = vm;
        }
    }
}

extern "C" void kernel_launch(void* const* d_in, const int* in_sizes, int n_in,
                              void* d_out, int out_size)
{
    const float* traj = (const float*)d_in[0];   // (192,80,4)
    const float* cent = (const float*)d_in[1];   // (192,5,4)
    const float* pd   = (const float*)d_in[2];   // (192,192)

    dim3 grid(NBLK, TT);   // (7, 80) = 560 blocks — single launch
    veh_kernel<<<grid, THREADS>>>(traj, cent, pd, (float*)d_out);
}

// round 12
// speedup vs baseline: 1.3375x; 1.1800x over previous
#include <cuda_runtime.h>
#include <math.h>

#define NA 192
#define TT 80
#define NC 5
#define THREADS 256
#define NTILE 21            // upper-triangular 32x32 tiles of 192x192
#define TPB 3               // tiles per block
#define NBLK (NTILE / TPB)  // 7
#define PLANE (NC * NA)     // 960 floats per coordinate plane
#define TP 33               // transpose tile pitch (conflict-free)

typedef unsigned long long u64;

__constant__ int c_bi[NTILE] = {0,0,0,0,0,0, 1,1,1,1,1, 2,2,2,2, 3,3,3, 4,4, 5};
__constant__ int c_bj[NTILE] = {0,1,2,3,4,5, 1,2,3,4,5, 2,3,4,5, 3,4,5, 4,5, 5};

#define PK2(dst, v)   asm("mov.b64 %0, {%1, %1};" : "=l"(dst) : "f"(v))
#define SUB2(d,a,b)   asm("sub.rn.f32x2 %0, %1, %2;" : "=l"(d) : "l"(a), "l"(b))
#define MUL2(d,a,b)   asm("mul.rn.f32x2 %0, %1, %2;" : "=l"(d) : "l"(a), "l"(b))
#define FMA2(d,a,b,c) asm("fma.rn.f32x2 %0, %1, %2, %3;" : "=l"(d) : "l"(a), "l"(b), "l"(c))
#define UNPK2(lo,hi,v) asm("mov.b64 {%0, %1}, %2;" : "=f"(lo), "=f"(hi) : "l"(v))

// scalar tail: closed-form min over the 5 collinear i-circles
// d2min = d2_0 + t^2 - 2 t g, t = clamp(rint(g/s),0,4)*s
__device__ __forceinline__ void jtail(float g, float d20, float s, float invs,
                                      float& macc)
{
    float c = rintf(g * invs);
    c = fminf(fmaxf(c, 0.0f), 4.0f);
    const float tt = c * s;
    const float rr = fmaf(-2.0f, g, tt);     // t - 2g
    const float d2m = fmaf(tt, rr, d20);
    macc = fminf(macc, d2m);
}

// ---- single fused kernel: build slab once, then 3 pair tiles ----
__global__ void __launch_bounds__(THREADS)
veh_kernel(const float* __restrict__ traj,   // (NA, T, 4)
           const float* __restrict__ cent,   // (NA, NC, 4)
           const float* __restrict__ pd,     // (NA, NA)
           float* __restrict__ out)
{
    const int t   = blockIdx.y;
    const int tid = threadIdx.x;

    __shared__ __align__(16) float s[2 * PLANE];       // world x then y (7.5 KB)
    __shared__ float shx[NA], shy[NA], ss[NA], sinv[NA];
    __shared__ float tpen[32 * TP];
    __shared__ float tmsk[32 * TP];
    float* __restrict__ swx = s;
    float* __restrict__ swy = s + PLANE;

    // ---- build world circles + per-agent constants ----
    if (tid < NA) {
        const int a = tid;
        const float4 tr = *reinterpret_cast<const float4*>(traj + ((size_t)a * TT + t) * 4);
        float hx = tr.z, hy = tr.w;
        const float inv = rsqrtf(hx * hx + hy * hy);
        hx *= inv; hy *= inv;
        float cx0 = 0.f, cx1 = 0.f;
        #pragma unroll
        for (int c = 0; c < NC; ++c) {
            const float2 cc = *reinterpret_cast<const float2*>(cent + ((size_t)a * NC + c) * 4);
            if (c == 0) cx0 = cc.x;
            if (c == 1) cx1 = cc.x;
            swx[c * NA + a] = fmaf(hx, cc.x, fmaf(-hy, cc.y, tr.x));
            swy[c * NA + a] = fmaf(hy, cc.x, fmaf( hx, cc.y, tr.y));
        }
        shx[a]  = hx;
        shy[a]  = hy;
        const float sp = cx1 - cx0;      // circle spacing (> 0)
        ss[a]   = sp;
        sinv[a] = 1.0f / sp;
    }
    __syncthreads();

    const int r = tid >> 3;          // local i row 0..31
    const int q = tid & 7;           // quad column 0..7
    const size_t tbase = (size_t)t * (NA * NA);
    const size_t moff  = (size_t)TT * (NA * NA);

    #pragma unroll 1
    for (int it = 0; it < TPB; ++it) {
        const int tile = blockIdx.x * TPB + it;
        const int bi = c_bi[tile];
        const int bj = c_bj[tile];
        const int i  = bi * 32 + r;
        const int j0 = bj * 32 + q * 4;

        // i-state: c=0 circle + heading packed; spacing scalars
        u64 xi02, yi02, hx2, hy2;
        PK2(xi02, swx[i]);           // c=0 plane
        PK2(yi02, swy[i]);
        PK2(hx2, shx[i]);
        PK2(hy2, shy[i]);
        const float si   = ss[i];
        const float sinvi = sinv[i];

        float m0 = 3.4e38f, m1 = 3.4e38f, m2 = 3.4e38f, m3 = 3.4e38f;

        #pragma unroll
        for (int d = 0; d < NC; ++d) {
            const ulonglong2 xj = *reinterpret_cast<const ulonglong2*>(swx + d * NA + j0);
            const ulonglong2 yj = *reinterpret_cast<const ulonglong2*>(swy + d * NA + j0);

            u64 dx, dy, tt2, d20, g2;
            float gA, gB, dA, dB;

            // lane 0: j0, j0+1
            SUB2(dx, xj.x, xi02);
            SUB2(dy, yj.x, yi02);
            MUL2(tt2, dx, dx);
            FMA2(d20, dy, dy, tt2);
            MUL2(g2, hx2, dx);
            FMA2(g2, hy2, dy, g2);
            UNPK2(gA, gB, g2);
            UNPK2(dA, dB, d20);
            jtail(gA, dA, si, sinvi, m0);
            jtail(gB, dB, si, sinvi, m1);

            // lane 1: j0+2, j0+3
            SUB2(dx, xj.y, xi02);
            SUB2(dy, yj.y, yi02);
            MUL2(tt2, dx, dx);
            FMA2(d20, dy, dy, tt2);
            MUL2(g2, hx2, dx);
            FMA2(g2, hy2, dy, g2);
            UNPK2(gA, gB, g2);
            UNPK2(dA, dB, d20);
            jtail(gA, dA, si, sinvi, m2);
            jtail(gB, dB, si, sinvi, m3);
        }

        const float mv[4] = {m0, m1, m2, m3};

        const int idx = i * NA + j0;
        const float4 p4 = *reinterpret_cast<const float4*>(pd + idx);
        const float pv[4] = {p4.x, p4.y, p4.z, p4.w};

        float4 pen, msk;
        float* penp = &pen.x;
        float* mskp = &msk.x;
        #pragma unroll
        for (int k = 0; k < 4; ++k) {
            // clamp (fma form can give tiny negatives on the diagonal) + rsqrt guard
            const float m2e = fmaxf(mv[k], 0.0f) + 1e-30f;
            float rr, ip;
            asm("rsqrt.approx.f32 %0, %1;" : "=f"(rr) : "f"(m2e));
            asm("rcp.approx.f32 %0, %1;"   : "=f"(ip) : "f"(pv[k]));
            const float mind = m2e * rr;           // = sqrt(m2e)
            penp[k] = fmaf(-mind, ip, 1.0f);
            // sqrt monotone: mind <= p  <=>  m2 <= p^2 ; diagonal excluded by i != j
            mskp[k] = (mv[k] <= pv[k] * pv[k] && i != j0 + k) ? 1.0f : 0.0f;
        }

        // direct tile write
        *reinterpret_cast<float4*>(out + tbase + idx) = pen;
        *reinterpret_cast<float4*>(out + moff + tbase + idx) = msk;

        // mirrored tile write (off-diagonal tiles only; block-uniform branch)
        if (bi != bj) {
            __syncthreads();    // protect tpen/tmsk reuse across iterations
            #pragma unroll
            for (int k = 0; k < 4; ++k) {
                tpen[(q * 4 + k) * TP + r] = penp[k];   // [local j][local i]
                tmsk[(q * 4 + k) * TP + r] = mskp[k];
            }
            __syncthreads();

            float4 vp, vm;
            float* vpp = &vp.x;
            float* vmp = &vm.x;
            #pragma unroll
            for (int k = 0; k < 4; ++k) {
                vpp[k] = tpen[r * TP + q * 4 + k];
                vmp[k] = tmsk[r * TP + q * 4 + k];
            }
            const int ot = (bj * 32 + r) * NA + bi * 32 + q * 4;
            *reinterpret_cast<float4*>(out + tbase + ot) = vp;
            *reinterpret_cast<float4*>(out + moff + tbase + ot) = vm;
        }
    }
}

extern "C" void kernel_launch(void* const* d_in, const int* in_sizes, int n_in,
                              void* d_out, int out_size)
{
    const float* traj = (const float*)d_in[0];   // (192,80,4)
    const float* cent = (const float*)d_in[1];   // (192,5,4)
    const float* pd   = (const float*)d_in[2];   // (192,192)

    dim3 grid(NBLK, TT);   // (7, 80) = 560 blocks — single launch
    veh_kernel<<<grid, THREADS>>>(traj, cent, pd, (float*)d_out);
}

// round 13
// speedup vs baseline: 1.3409x; 1.0025x over previous
#include <cuda_runtime.h>
#include <math.h>

#define NA 192
#define TT 80
#define NC 5
#define THREADS 256
#define NTILE 21            // upper-triangular 32x32 tiles of 192x192
#define TPB 3               // tiles per block
#define NBLK (NTILE / TPB)  // 7
#define TP 33               // transpose tile pitch (conflict-free)

typedef unsigned long long u64;

__constant__ int c_bi[NTILE] = {0,0,0,0,0,0, 1,1,1,1,1, 2,2,2,2, 3,3,3, 4,4, 5};
__constant__ int c_bj[NTILE] = {0,1,2,3,4,5, 1,2,3,4,5, 2,3,4,5, 3,4,5, 4,5, 5};

#define PK2(dst, v)   asm("mov.b64 %0, {%1, %1};" : "=l"(dst) : "f"(v))
#define SUB2(d,a,b)   asm("sub.rn.f32x2 %0, %1, %2;" : "=l"(d) : "l"(a), "l"(b))
#define MUL2(d,a,b)   asm("mul.rn.f32x2 %0, %1, %2;" : "=l"(d) : "l"(a), "l"(b))
#define ADD2(d,a,b)   asm("add.rn.f32x2 %0, %1, %2;" : "=l"(d) : "l"(a), "l"(b))
#define ADD2ACC(a,b)  asm("add.rn.f32x2 %0, %0, %1;" : "+l"(a) : "l"(b))
#define FMA2(d,a,b,c) asm("fma.rn.f32x2 %0, %1, %2, %3;" : "=l"(d) : "l"(a), "l"(b), "l"(c))
#define UNPK2(lo,hi,v) asm("mov.b64 {%0, %1}, %2;" : "=f"(lo), "=f"(hi) : "l"(v))

// closed-form min over the 5 collinear i-circles:
// d2min = d20 + t^2 - 2 t g,  t = rint(saturate(g/(4s))*4)*s
__device__ __forceinline__ void jtail(float g, float d20, float s, float inv4s,
                                      float& macc)
{
    const float c4 = __saturatef(g * inv4s);   // clamp to [0,1]
    const float c  = rintf(c4 * 4.0f);         // {0,1,2,3,4}
    const float tt = c * s;
    const float rr = fmaf(-2.0f, g, tt);       // t - 2g
    macc = fminf(macc, fmaf(tt, rr, d20));
}

// ---- single fused kernel ----
__global__ void __launch_bounds__(THREADS)
veh_kernel(const float* __restrict__ traj,   // (NA, T, 4)
           const float* __restrict__ cent,   // (NA, NC, 4)
           const float* __restrict__ pd,     // (NA, NA)
           float* __restrict__ out)
{
    const int t   = blockIdx.y;
    const int tid = threadIdx.x;

    // flat per-agent state (all 16B-aligned, NA=192 floats each)
    __shared__ __align__(16) float swx0[NA], swy0[NA];   // base circle (c=0)
    __shared__ __align__(16) float shx[NA],  shy[NA];    // unit heading
    __shared__ __align__(16) float svx[NA],  svy[NA];    // step vector s*h
    __shared__ __align__(16) float ss[NA],   sinv4[NA];  // spacing, 1/(4s)
    __shared__ float tpen[32 * TP];
    __shared__ float tmsk[32 * TP];

    // ---- prologue: base circle + per-agent constants ----
    if (tid < NA) {
        const int a = tid;
        const float4 tr = *reinterpret_cast<const float4*>(traj + ((size_t)a * TT + t) * 4);
        float hx = tr.z, hy = tr.w;
        const float inv = rsqrtf(hx * hx + hy * hy);
        hx *= inv; hy *= inv;
        const float cx0 = cent[(size_t)a * NC * 4];           // c=0 x (cy == 0)
        const float cx1 = cent[((size_t)a * NC + 1) * 4];     // c=1 x
        swx0[a] = fmaf(hx, cx0, tr.x);
        swy0[a] = fmaf(hy, cx0, tr.y);
        shx[a]  = hx;
        shy[a]  = hy;
        const float sp = cx1 - cx0;    // circle spacing (> 0)
        svx[a]  = sp * hx;
        svy[a]  = sp * hy;
        ss[a]   = sp;
        sinv4[a] = 0.25f / sp;
    }
    __syncthreads();

    const int r = tid >> 3;          // local i row 0..31
    const int q = tid & 7;           // quad column 0..7
    const size_t tbase = (size_t)t * (NA * NA);
    const size_t moff  = (size_t)TT * (NA * NA);

    #pragma unroll 1
    for (int it = 0; it < TPB; ++it) {
        const int tile = blockIdx.x * TPB + it;
        const int bi = c_bi[tile];
        const int bj = c_bj[tile];
        const int i  = bi * 32 + r;
        const int j0 = bj * 32 + q * 4;

        // i-state packed
        u64 xi2, yi2, hx2, hy2;
        PK2(xi2, swx0[i]);
        PK2(yi2, swy0[i]);
        PK2(hx2, shx[i]);
        PK2(hy2, shy[i]);
        const float si    = ss[i];
        const float inv4i = sinv4[i];

        // j-quad loads (once per tile): 4 LDS.128
        const ulonglong2 xj = *reinterpret_cast<const ulonglong2*>(swx0 + j0);
        const ulonglong2 yj = *reinterpret_cast<const ulonglong2*>(swy0 + j0);
        const ulonglong2 vx = *reinterpret_cast<const ulonglong2*>(svx + j0);
        const ulonglong2 vy = *reinterpret_cast<const ulonglong2*>(svy + j0);

        // lane A = (j0, j0+1), lane B = (j0+2, j0+3)
        u64 dxA, dyA, dxB, dyB, gA, gB, kA, kB, tA, d2A, d2B;
        SUB2(dxA, xj.x, xi2);
        SUB2(dyA, yj.x, yi2);
        SUB2(dxB, xj.y, xi2);
        SUB2(dyB, yj.y, yi2);
        MUL2(gA, hx2, dxA);  FMA2(gA, hy2, dyA, gA);    // g = h_i . Delta
        MUL2(gB, hx2, dxB);  FMA2(gB, hy2, dyB, gB);
        MUL2(kA, hx2, vx.x); FMA2(kA, hy2, vy.x, kA);   // kappa = h_i . (s_j h_j)
        MUL2(kB, hx2, vx.y); FMA2(kB, hy2, vy.y, kB);

        float m0 = 3.4e38f, m1 = 3.4e38f, m2 = 3.4e38f, m3 = 3.4e38f;

        #pragma unroll
        for (int d = 0; d < NC; ++d) {
            float ga, gb, da, db;

            MUL2(tA, dxA, dxA); FMA2(d2A, dyA, dyA, tA);
            MUL2(tA, dxB, dxB); FMA2(d2B, dyB, dyB, tA);

            UNPK2(ga, gb, gA); UNPK2(da, db, d2A);
            jtail(ga, da, si, inv4i, m0);
            jtail(gb, db, si, inv4i, m1);
            UNPK2(ga, gb, gB); UNPK2(da, db, d2B);
            jtail(ga, da, si, inv4i, m2);
            jtail(gb, db, si, inv4i, m3);

            if (d < NC - 1) {   // advance to next j circle
                ADD2ACC(dxA, vx.x); ADD2ACC(dyA, vy.x); ADD2ACC(gA, kA);
                ADD2ACC(dxB, vx.y); ADD2ACC(dyB, vy.y); ADD2ACC(gB, kB);
            }
        }

        const float mv[4] = {m0, m1, m2, m3};

        const int idx = i * NA + j0;
        const float4 p4 = *reinterpret_cast<const float4*>(pd + idx);
        const float pv[4] = {p4.x, p4.y, p4.z, p4.w};

        float4 pen, msk;
        float* penp = &pen.x;
        float* mskp = &msk.x;
        #pragma unroll
        for (int k = 0; k < 4; ++k) {
            const float m2e = fmaxf(mv[k], 0.0f) + 1e-30f;  // clamp + rsqrt guard
            float rr, ip;
            asm("rsqrt.approx.f32 %0, %1;" : "=f"(rr) : "f"(m2e));
            asm("rcp.approx.f32 %0, %1;"   : "=f"(ip) : "f"(pv[k]));
            const float mind = m2e * rr;           // = sqrt(m2e)
            penp[k] = fmaf(-mind, ip, 1.0f);
            // sqrt monotone: mind <= p  <=>  m2 <= p^2 ; diagonal excluded by i != j
            mskp[k] = (mv[k] <= pv[k] * pv[k] && i != j0 + k) ? 1.0f : 0.0f;
        }

        // direct tile write
        *reinterpret_cast<float4*>(out + tbase + idx) = pen;
        *reinterpret_cast<float4*>(out + moff + tbase + idx) = msk;

        // mirrored tile write (off-diagonal tiles only; block-uniform branch)
        if (bi != bj) {
            __syncthreads();    // protect tpen/tmsk reuse across iterations
            #pragma unroll
            for (int k = 0; k < 4; ++k) {
                tpen[(q * 4 + k) * TP + r] = penp[k];   // [local j][local i]
                tmsk[(q * 4 + k) * TP + r] = mskp[k];
            }
            __syncthreads();

            float4 vp, vm;
            float* vpp = &vp.x;
            float* vmp = &vm.x;
            #pragma unroll
            for (int k = 0; k < 4; ++k) {
                vpp[k] = tpen[r * TP + q * 4 + k];
                vmp[k] = tmsk[r * TP + q * 4 + k];
            }
            const int ot = (bj * 32 + r) * NA + bi * 32 + q * 4;
            *reinterpret_cast<float4*>(out + tbase + ot) = vp;
            *reinterpret_cast<float4*>(out + moff + tbase + ot) = vm;
        }
    }
}

extern "C" void kernel_launch(void* const* d_in, const int* in_sizes, int n_in,
                              void* d_out, int out_size)
{
    const float* traj = (const float*)d_in[0];   // (192,80,4)
    const float* cent = (const float*)d_in[1];   // (192,5,4)
    const float* pd   = (const float*)d_in[2];   // (192,192)

    dim3 grid(NBLK, TT);   // (7, 80) = 560 blocks — single launch
    veh_kernel<<<grid, THREADS>>>(traj, cent, pd, (float*)d_out);
}